// round 6
// baseline (speedup 1.0000x reference)
#include <cuda_runtime.h>
#include <cuda_fp16.h>
#include <cstdint>

// Problem constants
#define D 4096
#define C 512
#define T 2048

// Chunked-scan geometry
#define CHK   16                 // outputs per chunk
#define NCH   128                // T / CHK  (= GEMM N dimension)
#define WIN   24                 // warmup window (0.64^25 ~ 1.4e-5 truncation)
#define STEPS (WIN + CHK)        // 40 sequential batched steps
#define MT    32                 // M tiles (D / 128)
#define KSPLIT 4
#define KS_LEN (D / KSPLIT)      // 1024

// GEMM tiling
#define PITCH   72               // smem row pitch in halves (conflict-free ldmatrix)
#define PITCHB  144              // pitch in bytes
#define A_BYTES (128 * PITCHB)   // 18432
#define STAGE_BYTES (2 * A_BYTES)
#define NSTAGE  3
#define SMEM_TOTAL (NSTAGE * STAGE_BYTES)   // 110592 B

// ---------------------------------------------------------------------------
// Static device scratch (no runtime allocation allowed)
// ---------------------------------------------------------------------------
__device__ __align__(1024) __half g_Ah[(size_t)D * D];          // W_A fp16 (32 MB)
__device__ __align__(1024) __half g_WBh[(size_t)D * C];         // W_B fp16 (4 MB)
__device__ __align__(1024) __half g_uth[(size_t)T * C];         // u^T fp16 (2 MB)
__device__ __align__(1024) float  g_v[(size_t)T * D];           // v[t][d] fp32 (32 MB)
__device__ __align__(1024) float  g_part[(size_t)KSPLIT * NCH * D]; // partials (8 MB)
__device__ __align__(1024) __half g_Y[2][(size_t)NCH * D];      // state ping-pong [n][d]
__device__ int g_cnt[STEPS * MT];                               // combine counters

// ---------------------------------------------------------------------------
// PTX helpers (sm_80-era only; target PTX is compute_103 non-'a')
// ---------------------------------------------------------------------------
__device__ __forceinline__ uint32_t s2u(const void* p) {
    uint32_t a;
    asm("{ .reg .u64 t; cvta.to.shared.u64 t, %1; cvt.u32.u64 %0, t; }" : "=r"(a) : "l"(p));
    return a;
}
#define CPA16(s, g)  asm volatile("cp.async.cg.shared.global [%0], [%1], 16;" :: "r"(s), "l"(g) : "memory")
#define CPACOMMIT()  asm volatile("cp.async.commit_group;" ::: "memory")
#define CPAWAIT1()   asm volatile("cp.async.wait_group 1;" ::: "memory")

#define LDSM4(r, a)                                                             \
    asm volatile("ldmatrix.sync.aligned.m8n8.x4.shared.b16 {%0,%1,%2,%3}, [%4];" \
        : "=r"((r)[0]), "=r"((r)[1]), "=r"((r)[2]), "=r"((r)[3]) : "r"(a))

#define MMA16816(d, a, b0, b1)                                                  \
    asm volatile("mma.sync.aligned.m16n8k16.row.col.f32.f16.f16.f32 "           \
        "{%0,%1,%2,%3}, {%4,%5,%6,%7}, {%8,%9}, {%0,%1,%2,%3};"                 \
        : "+f"((d)[0]), "+f"((d)[1]), "+f"((d)[2]), "+f"((d)[3])                \
        : "r"((a)[0]), "r"((a)[1]), "r"((a)[2]), "r"((a)[3]), "r"(b0), "r"(b1))

// ---------------------------------------------------------------------------
// Shared GEMM mainloop: acc[mi][ni][4] += Aop[128 x K] * Bop[128 x K]^T
// 256 threads / 8 warps (2x4 warp grid, 64x32 per warp). 3-stage cp.async.
// A rows stride lda (halves), B rows stride ldb (both K-major).
// ---------------------------------------------------------------------------
__device__ __forceinline__ void load_stage(char* smem, int buf,
                                           const __half* Aop, int lda,
                                           const __half* Bop, int ldb,
                                           int kofs, int tid) {
    const uint32_t base = s2u(smem) + buf * STAGE_BYTES;
    #pragma unroll
    for (int p = 0; p < 4; p++) {
        int idx = p * 256 + tid;
        int row = idx >> 3, ch = idx & 7;
        CPA16(base + row * PITCHB + ch * 16,
              Aop + (size_t)row * lda + kofs + ch * 8);
    }
    const uint32_t bb = base + A_BYTES;
    #pragma unroll
    for (int p = 0; p < 4; p++) {
        int idx = p * 256 + tid;
        int row = idx >> 3, ch = idx & 7;
        CPA16(bb + row * PITCHB + ch * 16,
              Bop + (size_t)row * ldb + kofs + ch * 8);
    }
    CPACOMMIT();
}

__device__ __forceinline__ void gemm_main(char* smem,
                                          const __half* Aop, int lda,
                                          const __half* Bop, int ldb,
                                          int kIters, float acc[4][4][4]) {
    const int tid  = threadIdx.x;
    const int lane = tid & 31;
    const int wid  = tid >> 5;
    const int wm   = wid >> 2;   // 0..1  (64 rows each)
    const int wn   = wid & 3;    // 0..3  (32 cols each)

    load_stage(smem, 0, Aop, lda, Bop, ldb, 0, tid);
    load_stage(smem, 1, Aop, lda, Bop, ldb, 64, tid);

    const uint32_t sbase = s2u(smem);
    // ldmatrix lane address terms
    const uint32_t aLane = (uint32_t)(((wm * 64 + (lane & 15)) * PITCH + (lane >> 4) * 8) * 2);
    const uint32_t bLane = (uint32_t)(((wn * 32 + (lane & 7) + ((lane >> 4) << 3)) * PITCH
                                       + ((lane >> 3) & 1) * 8) * 2);

    for (int it = 0; it < kIters; ++it) {
        CPAWAIT1();
        __syncthreads();
        if (it + 2 < kIters)
            load_stage(smem, (it + 2) % NSTAGE, Aop, lda, Bop, ldb, (it + 2) * 64, tid);

        const uint32_t sA = sbase + (it % NSTAGE) * STAGE_BYTES;
        const uint32_t sB = sA + A_BYTES;
        const uint32_t aBase = sA + aLane;
        const uint32_t bBase = sB + bLane;

        #pragma unroll
        for (int kk = 0; kk < 4; kk++) {
            uint32_t a[4][4];
            #pragma unroll
            for (int mi = 0; mi < 4; mi++)
                LDSM4(a[mi], aBase + mi * 16 * PITCHB + kk * 32);
            uint32_t b[2][4];
            LDSM4(b[0], bBase + kk * 32);
            LDSM4(b[1], bBase + 16 * PITCHB + kk * 32);
            #pragma unroll
            for (int mi = 0; mi < 4; mi++)
                #pragma unroll
                for (int ni = 0; ni < 4; ni++)
                    MMA16816(acc[mi][ni], a[mi],
                             b[ni >> 1][(ni & 1) * 2], b[ni >> 1][(ni & 1) * 2 + 1]);
        }
    }
    __syncthreads();   // all reads of stage smem done before epilogue reuse
}

// Scatter accumulators into smem as sC[m][n] (pad 133 -> conflict-free col reads)
__device__ __forceinline__ void epilogue_to_smem(char* smem, float acc[4][4][4]) {
    float (*sC)[133] = reinterpret_cast<float (*)[133]>(smem);
    const int lane = threadIdx.x & 31;
    const int wid  = threadIdx.x >> 5;
    const int wm = wid >> 2, wn = wid & 3;
    const int r0 = wm * 64 + (lane >> 2);
    const int c0 = wn * 32 + (lane & 3) * 2;
    #pragma unroll
    for (int mi = 0; mi < 4; mi++)
        #pragma unroll
        for (int ni = 0; ni < 4; ni++) {
            int r = r0 + mi * 16, c = c0 + ni * 8;
            sC[r][c]         = acc[mi][ni][0];
            sC[r][c + 1]     = acc[mi][ni][1];
            sC[r + 8][c]     = acc[mi][ni][2];
            sC[r + 8][c + 1] = acc[mi][ni][3];
        }
    __syncthreads();
}

// ---------------------------------------------------------------------------
// Scan step kernel: Ynext = A * Ycur + V_step
// grid = 128 CTAs (32 m-tiles x 4 k-splits), 256 threads
// ---------------------------------------------------------------------------
__global__ void __launch_bounds__(256, 1)
scan_step_kernel(int step, float* __restrict__ out) {
    extern __shared__ char smem[];
    const int tid = threadIdx.x;
    const int mt = blockIdx.x >> 2;
    const int ks = blockIdx.x & 3;

    const __half* ycur  = g_Y[step & 1];
    __half*       ynext = g_Y[(step & 1) ^ 1];
    const __half* Aop = g_Ah + (size_t)mt * 128 * D + ks * KS_LEN;
    const __half* Bop = ycur + ks * KS_LEN;

    float acc[4][4][4];
    #pragma unroll
    for (int i = 0; i < 4; i++)
        #pragma unroll
        for (int j = 0; j < 4; j++)
            #pragma unroll
            for (int e = 0; e < 4; e++) acc[i][j][e] = 0.f;

    gemm_main(smem, Aop, D, Bop, D, KS_LEN / 64, acc);
    epilogue_to_smem(smem, acc);

    // Coalesced partial write: g_part[(ks*NCH + n)*D + m]
    float (*sC)[133] = reinterpret_cast<float (*)[133]>(smem);
    const int m = tid & 127;
    const int h = tid >> 7;
    #pragma unroll 4
    for (int i = 0; i < 64; i++) {
        int n = h * 64 + i;
        g_part[((size_t)(ks * NCH + n)) * D + mt * 128 + m] = sC[m][n];
    }

    __threadfence();
    __shared__ int flag;
    if (tid == 0)
        flag = (atomicAdd(&g_cnt[step * MT + mt], 1) == KSPLIT - 1) ? 1 : 0;
    __syncthreads();

    if (flag) {
        __threadfence();
        const int mg = mt * 128 + m;
        const float* p0 = g_part + mg;
        #pragma unroll 2
        for (int i = 0; i < 64; i++) {
            int n = h * 64 + i;
            float s = __ldcg(p0 + (size_t)n * D)
                    + __ldcg(p0 + (size_t)(NCH + n) * D)
                    + __ldcg(p0 + (size_t)(2 * NCH + n) * D)
                    + __ldcg(p0 + (size_t)(3 * NCH + n) * D);
            int q = n * CHK - WIN + step;
            if (q >= 0) s += g_v[(size_t)q * D + mg];
            ynext[(size_t)n * D + mg] = __float2half(s);
            if (step >= WIN) out[(size_t)q * D + mg] = s;
        }
    }
}

// ---------------------------------------------------------------------------
// v GEMM: g_v[t][d] = sum_c WB[d][c]*u[c][t] + bA[d] + bB[d]
// grid = 512 CTAs (32 m-tiles x 16 t-tiles), 256 threads
// ---------------------------------------------------------------------------
__global__ void __launch_bounds__(256, 1)
vgemm_tc_kernel(const float* __restrict__ bA, const float* __restrict__ bB) {
    extern __shared__ char smem[];
    const int tid = threadIdx.x;
    const int mt = blockIdx.x & 31;
    const int nt = blockIdx.x >> 5;

    const __half* Aop = g_WBh + (size_t)mt * 128 * C;
    const __half* Bop = g_uth + (size_t)nt * 128 * C;

    float acc[4][4][4];
    #pragma unroll
    for (int i = 0; i < 4; i++)
        #pragma unroll
        for (int j = 0; j < 4; j++)
            #pragma unroll
            for (int e = 0; e < 4; e++) acc[i][j][e] = 0.f;

    gemm_main(smem, Aop, C, Bop, C, C / 64, acc);
    epilogue_to_smem(smem, acc);

    float (*sC)[133] = reinterpret_cast<float (*)[133]>(smem);
    const int m = tid & 127;
    const int h = tid >> 7;
    const int mg = mt * 128 + m;
    const float bias = bA[mg] + bB[mg];
    #pragma unroll 4
    for (int i = 0; i < 64; i++) {
        int n = h * 64 + i;
        int t = nt * 128 + n;
        g_v[(size_t)t * D + mg] = sC[m][n] + bias;
    }
}

// ---------------------------------------------------------------------------
// Conversion / setup kernels
// ---------------------------------------------------------------------------
__global__ void convA_kernel(const float* __restrict__ WA) {
    size_t i = (size_t)blockIdx.x * blockDim.x + threadIdx.x;
    const float4* W4 = reinterpret_cast<const float4*>(WA);
    __half2* A2 = reinterpret_cast<__half2*>(g_Ah);
    float4 w = W4[i];
    A2[2 * i + 0] = __floats2half2_rn(w.x, w.y);
    A2[2 * i + 1] = __floats2half2_rn(w.z, w.w);
}

__global__ void convWB_kernel(const float* __restrict__ WB) {
    size_t i = (size_t)blockIdx.x * blockDim.x + threadIdx.x;
    const float4* W4 = reinterpret_cast<const float4*>(WB);
    __half2* A2 = reinterpret_cast<__half2*>(g_WBh);
    float4 w = W4[i];
    A2[2 * i + 0] = __floats2half2_rn(w.x, w.y);
    A2[2 * i + 1] = __floats2half2_rn(w.z, w.w);
}

// u [C][T] fp32 -> g_uth [T][C] fp16
__global__ void transu_kernel(const float* __restrict__ u) {
    __shared__ float tile[32][33];
    const int t0 = blockIdx.x * 32;
    const int c0 = blockIdx.y * 32;
    const int x = threadIdx.x, y = threadIdx.y;
    #pragma unroll
    for (int j = 0; j < 32; j += 8)
        tile[y + j][x] = u[(size_t)(c0 + y + j) * T + t0 + x];
    __syncthreads();
    #pragma unroll
    for (int j = 0; j < 32; j += 8)
        g_uth[(size_t)(t0 + y + j) * C + c0 + x] = __float2half(tile[x][y + j]);
}

// g_v[0][:] += W_A(fp32) @ x0  (exact x0 injection; runs AFTER vgemm)
__global__ void ax0_kernel(const float* __restrict__ WA, const float* __restrict__ x0) {
    const int r = blockIdx.x * 8 + (threadIdx.x >> 5);
    const int lane = threadIdx.x & 31;
    const float* row = WA + (size_t)r * D;
    float a = 0.f;
    #pragma unroll 4
    for (int k = lane; k < D; k += 32) a += row[k] * x0[k];
    #pragma unroll
    for (int off = 16; off > 0; off >>= 1) a += __shfl_down_sync(0xffffffffu, a, off);
    if (lane == 0) g_v[r] += a;
}

// Zero initial state Y[0] and combine counters (must run every replay)
__global__ void zero_kernel() {
    size_t i = (size_t)blockIdx.x * blockDim.x + threadIdx.x;
    uint32_t* y0 = reinterpret_cast<uint32_t*>(g_Y[0]);
    if (i < (size_t)NCH * D / 2) y0[i] = 0u;
    if (i < STEPS * MT) g_cnt[i] = 0;
}

// ---------------------------------------------------------------------------
// Entry point
// ---------------------------------------------------------------------------
extern "C" void kernel_launch(void* const* d_in, const int* in_sizes, int n_in,
                              void* d_out, int out_size)
{
    const float* x0 = (const float*)d_in[0];   // [D]
    const float* u  = (const float*)d_in[1];   // [C, T]
    const float* WA = (const float*)d_in[2];   // [D, D]
    const float* bA = (const float*)d_in[3];   // [D]
    const float* WB = (const float*)d_in[4];   // [D, C]
    const float* bB = (const float*)d_in[5];   // [D]
    float* out = (float*)d_out;                // [T, D]
    (void)in_sizes; (void)n_in; (void)out_size;

    // Opt into >48KB dynamic smem. Skip while a graph capture is active
    // (attributes were already applied during the correctness call).
    cudaStreamCaptureStatus cap = cudaStreamCaptureStatusNone;
    cudaStreamIsCapturing(0, &cap);
    if (cap == cudaStreamCaptureStatusNone) {
        cudaFuncSetAttribute(scan_step_kernel,
                             cudaFuncAttributeMaxDynamicSharedMemorySize, SMEM_TOTAL);
        cudaFuncSetAttribute(vgemm_tc_kernel,
                             cudaFuncAttributeMaxDynamicSharedMemorySize, SMEM_TOTAL);
    }

    // Setup
    convA_kernel<<<(unsigned)((size_t)D * D / 4 / 256), 256>>>(WA);
    convWB_kernel<<<(unsigned)((size_t)D * C / 4 / 256), 256>>>(WB);
    transu_kernel<<<dim3(T / 32, C / 32), dim3(32, 8)>>>(u);
    vgemm_tc_kernel<<<512, 256, SMEM_TOTAL>>>(bA, bB);
    ax0_kernel<<<D / 8, 256>>>(WA, x0);
    zero_kernel<<<1024, 256>>>();

    // 40 sequential batched-recurrence steps
    for (int s = 0; s < STEPS; ++s)
        scan_step_kernel<<<MT * KSPLIT, 256, SMEM_TOTAL>>>(s, out);
}

// round 7
// speedup vs baseline: 1.6348x; 1.6348x over previous
#include <cuda_runtime.h>
#include <cuda_fp16.h>
#include <cstdint>

// Problem constants
#define D 4096
#define C 512
#define T 2048

// Chunked-scan geometry
#define CHK   16                 // outputs per chunk
#define NCH   128                // T / CHK  (= GEMM N dimension)
#define WIN   20                 // warmup window (0.64^21 ~ 8.6e-5 truncation)
#define STEPS (WIN + CHK)        // 36 sequential batched steps
#define MT    32                 // M tiles (D / 128)
#define KSPLIT 4
#define KS_LEN (D / KSPLIT)      // 1024
#define KITERS (KS_LEN / 64)     // 16

// GEMM tiling
#define PITCH   72               // smem row pitch in halves (conflict-free ldmatrix)
#define PITCHB  144              // pitch in bytes
#define A_BYTES (128 * PITCHB)   // 18432
#define STAGE_BYTES (2 * A_BYTES)
#define NSTAGE  4
#define SMEM_TOTAL (NSTAGE * STAGE_BYTES)   // 147456 B

// ---------------------------------------------------------------------------
// Static device scratch (no runtime allocation allowed)
// ---------------------------------------------------------------------------
__device__ __align__(1024) __half g_Ah[(size_t)D * D];          // W_A fp16 (32 MB)
__device__ __align__(1024) __half g_WBh[(size_t)D * C];         // W_B fp16 (4 MB)
__device__ __align__(1024) __half g_uth[(size_t)T * C];         // u^T fp16 (2 MB)
__device__ __align__(1024) float  g_v[(size_t)T * D];           // v[t][d] fp32 (32 MB)
__device__ __align__(1024) float  g_part[(size_t)KSPLIT * NCH * D]; // partials (8 MB)
__device__ __align__(1024) __half g_Y[2][(size_t)NCH * D];      // state ping-pong [n][d]

// Grid barrier state (reset by zero_kernel each replay)
__device__ unsigned          g_count;
__device__ volatile unsigned g_gen;

// ---------------------------------------------------------------------------
// PTX helpers (sm_80-era only; target PTX is compute_103 non-'a')
// ---------------------------------------------------------------------------
__device__ __forceinline__ uint32_t s2u(const void* p) {
    uint32_t a;
    asm("{ .reg .u64 t; cvta.to.shared.u64 t, %1; cvt.u32.u64 %0, t; }" : "=r"(a) : "l"(p));
    return a;
}
#define CPA16(s, g)  asm volatile("cp.async.cg.shared.global [%0], [%1], 16;" :: "r"(s), "l"(g) : "memory")
#define CPACOMMIT()  asm volatile("cp.async.commit_group;" ::: "memory")
#define CPAWAIT2()   asm volatile("cp.async.wait_group 2;" ::: "memory")

#define LDSM4(r, a)                                                             \
    asm volatile("ldmatrix.sync.aligned.m8n8.x4.shared.b16 {%0,%1,%2,%3}, [%4];" \
        : "=r"((r)[0]), "=r"((r)[1]), "=r"((r)[2]), "=r"((r)[3]) : "r"(a))

#define MMA16816(d, a, b0, b1)                                                  \
    asm volatile("mma.sync.aligned.m16n8k16.row.col.f32.f16.f16.f32 "           \
        "{%0,%1,%2,%3}, {%4,%5,%6,%7}, {%8,%9}, {%0,%1,%2,%3};"                 \
        : "+f"((d)[0]), "+f"((d)[1]), "+f"((d)[2]), "+f"((d)[3])                \
        : "r"((a)[0]), "r"((a)[1]), "r"((a)[2]), "r"((a)[3]), "r"(b0), "r"(b1))

// ---------------------------------------------------------------------------
// Shared GEMM mainloop: acc[mi][ni][4] += Aop[128 x K] * Bop[128 x K]^T
// 256 threads / 8 warps (2x4 warp grid, 64x32 per warp). 4-stage cp.async.
// ---------------------------------------------------------------------------
__device__ __forceinline__ void load_stage(uint32_t sbase, int buf,
                                           const __half* Aop, int lda,
                                           const __half* Bop, int ldb,
                                           int kofs, int tid) {
    const uint32_t base = sbase + buf * STAGE_BYTES;
    #pragma unroll
    for (int p = 0; p < 4; p++) {
        int idx = p * 256 + tid;
        int row = idx >> 3, ch = idx & 7;
        CPA16(base + row * PITCHB + ch * 16,
              Aop + (size_t)row * lda + kofs + ch * 8);
    }
    const uint32_t bb = base + A_BYTES;
    #pragma unroll
    for (int p = 0; p < 4; p++) {
        int idx = p * 256 + tid;
        int row = idx >> 3, ch = idx & 7;
        CPA16(bb + row * PITCHB + ch * 16,
              Bop + (size_t)row * ldb + kofs + ch * 8);
    }
    CPACOMMIT();
}

__device__ __forceinline__ void gemm_main(uint32_t sbase,
                                          const __half* Aop, int lda,
                                          const __half* Bop, int ldb,
                                          int kIters, float acc[4][4][4]) {
    const int tid  = threadIdx.x;
    const int lane = tid & 31;
    const int wid  = tid >> 5;
    const int wm   = wid >> 2;   // 0..1  (64 rows each)
    const int wn   = wid & 3;    // 0..3  (32 cols each)

    load_stage(sbase, 0, Aop, lda, Bop, ldb, 0, tid);
    load_stage(sbase, 1, Aop, lda, Bop, ldb, 64, tid);
    load_stage(sbase, 2, Aop, lda, Bop, ldb, 128, tid);

    const uint32_t aLane = (uint32_t)(((wm * 64 + (lane & 15)) * PITCH + (lane >> 4) * 8) * 2);
    const uint32_t bLane = (uint32_t)(((wn * 32 + (lane & 7) + ((lane >> 4) << 3)) * PITCH
                                       + ((lane >> 3) & 1) * 8) * 2);

    for (int it = 0; it < kIters; ++it) {
        CPAWAIT2();
        __syncthreads();
        if (it + 3 < kIters)
            load_stage(sbase, (it + 3) & 3, Aop, lda, Bop, ldb, (it + 3) * 64, tid);
        else
            CPACOMMIT();   // keep group-count invariant

        const uint32_t sA = sbase + (it & 3) * STAGE_BYTES;
        const uint32_t aBase = sA + aLane;
        const uint32_t bBase = sA + A_BYTES + bLane;

        #pragma unroll
        for (int kk = 0; kk < 4; kk++) {
            uint32_t a[4][4];
            #pragma unroll
            for (int mi = 0; mi < 4; mi++)
                LDSM4(a[mi], aBase + mi * 16 * PITCHB + kk * 32);
            uint32_t b[2][4];
            LDSM4(b[0], bBase + kk * 32);
            LDSM4(b[1], bBase + 16 * PITCHB + kk * 32);
            #pragma unroll
            for (int mi = 0; mi < 4; mi++)
                #pragma unroll
                for (int ni = 0; ni < 4; ni++)
                    MMA16816(acc[mi][ni], a[mi],
                             b[ni >> 1][(ni & 1) * 2], b[ni >> 1][(ni & 1) * 2 + 1]);
        }
    }
    __syncthreads();   // all stage-smem reads done before epilogue reuse
}

// Scatter accumulators into smem as sC[m][n] (pad 133 -> conflict-free col reads)
__device__ __forceinline__ void epilogue_to_smem(char* smem, float acc[4][4][4]) {
    float (*sC)[133] = reinterpret_cast<float (*)[133]>(smem);
    const int lane = threadIdx.x & 31;
    const int wid  = threadIdx.x >> 5;
    const int wm = wid >> 2, wn = wid & 3;
    const int r0 = wm * 64 + (lane >> 2);
    const int c0 = wn * 32 + (lane & 3) * 2;
    #pragma unroll
    for (int mi = 0; mi < 4; mi++)
        #pragma unroll
        for (int ni = 0; ni < 4; ni++) {
            int r = r0 + mi * 16, c = c0 + ni * 8;
            sC[r][c]         = acc[mi][ni][0];
            sC[r][c + 1]     = acc[mi][ni][1];
            sC[r + 8][c]     = acc[mi][ni][2];
            sC[r + 8][c + 1] = acc[mi][ni][3];
        }
    __syncthreads();
}

// ---------------------------------------------------------------------------
// Grid-wide software barrier (all 128 CTAs co-resident; R1-validated pattern)
// ---------------------------------------------------------------------------
__device__ __forceinline__ void grid_barrier(unsigned target) {
    __threadfence();
    __syncthreads();
    if (threadIdx.x == 0) {
        unsigned old = atomicAdd(&g_count, 1u);
        if (old == (unsigned)(gridDim.x - 1)) {
            atomicExch(&g_count, 0u);
            __threadfence();
            g_gen = target;
        } else {
            while (g_gen != target) { }
            __threadfence();
        }
    }
    __syncthreads();
}

// ---------------------------------------------------------------------------
// Persistent scan kernel: runs all STEPS batched-recurrence steps.
// grid = 128 CTAs (32 m-tiles x 4 k-splits), 256 threads, 1 CTA/SM.
// ---------------------------------------------------------------------------
__global__ void __launch_bounds__(256, 1)
scan_persist_kernel(float* __restrict__ out) {
    extern __shared__ char smem[];
    const uint32_t sbase = s2u(smem);
    const int tid = threadIdx.x;
    const int mt = blockIdx.x >> 2;
    const int ks = blockIdx.x & 3;

    const __half* Aop = g_Ah + (size_t)mt * 128 * D + ks * KS_LEN;

    const int m  = tid & 127;
    const int h  = tid >> 7;
    const int mg = mt * 128 + m;

    unsigned gen = 0;

    for (int step = 0; step < STEPS; ++step) {
        const __half* ycur  = g_Y[step & 1];
        __half*       ynext = g_Y[(step & 1) ^ 1];
        const __half* Bop = ycur + ks * KS_LEN;

        float acc[4][4][4];
        #pragma unroll
        for (int i = 0; i < 4; i++)
            #pragma unroll
            for (int j = 0; j < 4; j++)
                #pragma unroll
                for (int e = 0; e < 4; e++) acc[i][j][e] = 0.f;

        gemm_main(sbase, Aop, D, Bop, D, KITERS, acc);
        epilogue_to_smem(smem, acc);

        // Coalesced partial write: g_part[(ks*NCH + n)*D + m]
        float (*sC)[133] = reinterpret_cast<float (*)[133]>(smem);
        #pragma unroll 4
        for (int i = 0; i < 64; i++) {
            int n = h * 64 + i;
            g_part[((size_t)(ks * NCH + n)) * D + mt * 128 + m] = sC[m][n];
        }

        grid_barrier(++gen);   // all partials visible

        // Distributed combine: this CTA owns n in [ks*32, ks*32+32)
        {
            const float* p0 = g_part + mg;
            #pragma unroll 2
            for (int i = 0; i < 16; i++) {
                int n = ks * 32 + h * 16 + i;
                float s = __ldcg(p0 + (size_t)n * D)
                        + __ldcg(p0 + (size_t)(NCH + n) * D)
                        + __ldcg(p0 + (size_t)(2 * NCH + n) * D)
                        + __ldcg(p0 + (size_t)(3 * NCH + n) * D);
                int q = n * CHK - WIN + step;
                if (q >= 0) s += g_v[(size_t)q * D + mg];
                ynext[(size_t)n * D + mg] = __float2half(s);
                if (step >= WIN) out[(size_t)q * D + mg] = s;
            }
        }

        grid_barrier(++gen);   // ynext visible before next step's B reads
    }
}

// ---------------------------------------------------------------------------
// v GEMM: g_v[t][d] = sum_c WB[d][c]*u[c][t] + bA[d] + bB[d]
// grid = 512 CTAs (32 m-tiles x 16 t-tiles), 256 threads
// ---------------------------------------------------------------------------
__global__ void __launch_bounds__(256, 1)
vgemm_tc_kernel(const float* __restrict__ bA, const float* __restrict__ bB) {
    extern __shared__ char smem[];
    const uint32_t sbase = s2u(smem);
    const int tid = threadIdx.x;
    const int mt = blockIdx.x & 31;
    const int nt = blockIdx.x >> 5;

    const __half* Aop = g_WBh + (size_t)mt * 128 * C;
    const __half* Bop = g_uth + (size_t)nt * 128 * C;

    float acc[4][4][4];
    #pragma unroll
    for (int i = 0; i < 4; i++)
        #pragma unroll
        for (int j = 0; j < 4; j++)
            #pragma unroll
            for (int e = 0; e < 4; e++) acc[i][j][e] = 0.f;

    gemm_main(sbase, Aop, C, Bop, C, C / 64, acc);
    epilogue_to_smem(smem, acc);

    float (*sC)[133] = reinterpret_cast<float (*)[133]>(smem);
    const int m = tid & 127;
    const int h = tid >> 7;
    const int mg = mt * 128 + m;
    const float bias = bA[mg] + bB[mg];
    #pragma unroll 4
    for (int i = 0; i < 64; i++) {
        int n = h * 64 + i;
        int t = nt * 128 + n;
        g_v[(size_t)t * D + mg] = sC[m][n] + bias;
    }
}

// ---------------------------------------------------------------------------
// Conversion / setup kernels
// ---------------------------------------------------------------------------
__global__ void convA_kernel(const float* __restrict__ WA) {
    size_t i = (size_t)blockIdx.x * blockDim.x + threadIdx.x;
    const float4* W4 = reinterpret_cast<const float4*>(WA);
    __half2* A2 = reinterpret_cast<__half2*>(g_Ah);
    float4 w = W4[i];
    A2[2 * i + 0] = __floats2half2_rn(w.x, w.y);
    A2[2 * i + 1] = __floats2half2_rn(w.z, w.w);
}

__global__ void convWB_kernel(const float* __restrict__ WB) {
    size_t i = (size_t)blockIdx.x * blockDim.x + threadIdx.x;
    const float4* W4 = reinterpret_cast<const float4*>(WB);
    __half2* A2 = reinterpret_cast<__half2*>(g_WBh);
    float4 w = W4[i];
    A2[2 * i + 0] = __floats2half2_rn(w.x, w.y);
    A2[2 * i + 1] = __floats2half2_rn(w.z, w.w);
}

// u [C][T] fp32 -> g_uth [T][C] fp16
__global__ void transu_kernel(const float* __restrict__ u) {
    __shared__ float tile[32][33];
    const int t0 = blockIdx.x * 32;
    const int c0 = blockIdx.y * 32;
    const int x = threadIdx.x, y = threadIdx.y;
    #pragma unroll
    for (int j = 0; j < 32; j += 8)
        tile[y + j][x] = u[(size_t)(c0 + y + j) * T + t0 + x];
    __syncthreads();
    #pragma unroll
    for (int j = 0; j < 32; j += 8)
        g_uth[(size_t)(t0 + y + j) * C + c0 + x] = __float2half(tile[x][y + j]);
}

// g_v[0][:] += W_A(fp32) @ x0  (exact x0 injection; runs AFTER vgemm)
__global__ void ax0_kernel(const float* __restrict__ WA, const float* __restrict__ x0) {
    const int r = blockIdx.x * 8 + (threadIdx.x >> 5);
    const int lane = threadIdx.x & 31;
    const float* row = WA + (size_t)r * D;
    float a = 0.f;
    #pragma unroll 4
    for (int k = lane; k < D; k += 32) a += row[k] * x0[k];
    #pragma unroll
    for (int off = 16; off > 0; off >>= 1) a += __shfl_down_sync(0xffffffffu, a, off);
    if (lane == 0) g_v[r] += a;
}

// Zero initial state Y[0] and barrier state (must run every replay)
__global__ void zero_kernel() {
    size_t i = (size_t)blockIdx.x * blockDim.x + threadIdx.x;
    uint32_t* y0 = reinterpret_cast<uint32_t*>(g_Y[0]);
    if (i < (size_t)NCH * D / 2) y0[i] = 0u;
    if (i == 0) { g_count = 0u; g_gen = 0u; }
}

// ---------------------------------------------------------------------------
// Entry point
// ---------------------------------------------------------------------------
extern "C" void kernel_launch(void* const* d_in, const int* in_sizes, int n_in,
                              void* d_out, int out_size)
{
    const float* x0 = (const float*)d_in[0];   // [D]
    const float* u  = (const float*)d_in[1];   // [C, T]
    const float* WA = (const float*)d_in[2];   // [D, D]
    const float* bA = (const float*)d_in[3];   // [D]
    const float* WB = (const float*)d_in[4];   // [D, C]
    const float* bB = (const float*)d_in[5];   // [D]
    float* out = (float*)d_out;                // [T, D]
    (void)in_sizes; (void)n_in; (void)out_size;

    // Opt into >48KB dynamic smem. Skip while a graph capture is active
    // (attributes were already applied during the correctness call).
    cudaStreamCaptureStatus cap = cudaStreamCaptureStatusNone;
    cudaStreamIsCapturing(0, &cap);
    if (cap == cudaStreamCaptureStatusNone) {
        cudaFuncSetAttribute(scan_persist_kernel,
                             cudaFuncAttributeMaxDynamicSharedMemorySize, SMEM_TOTAL);
        cudaFuncSetAttribute(vgemm_tc_kernel,
                             cudaFuncAttributeMaxDynamicSharedMemorySize, SMEM_TOTAL);
    }

    // Setup
    convA_kernel<<<(unsigned)((size_t)D * D / 4 / 256), 256>>>(WA);
    convWB_kernel<<<(unsigned)((size_t)D * C / 4 / 256), 256>>>(WB);
    transu_kernel<<<dim3(T / 32, C / 32), dim3(32, 8)>>>(u);
    vgemm_tc_kernel<<<512, 256, SMEM_TOTAL>>>(bA, bB);
    ax0_kernel<<<D / 8, 256>>>(WA, x0);
    zero_kernel<<<1024, 256>>>();

    // All 36 batched-recurrence steps in one persistent launch
    scan_persist_kernel<<<MT * KSPLIT, 256, SMEM_TOTAL>>>(out);
}

// round 9
// speedup vs baseline: 1.7153x; 1.0493x over previous
#include <cuda_runtime.h>
#include <cuda_fp16.h>
#include <cstdint>

// Problem constants
#define D 4096
#define C 512
#define T 2048

// Chunked-scan geometry
#define CHK   16                 // outputs per chunk
#define NCH   128                // T / CHK  (= GEMM N dimension)
#define WIN   20                 // warmup window (0.64^21 ~ 8.6e-5 truncation)
#define STEPS (WIN + CHK)        // 36 sequential batched steps
#define MT    32                 // M tiles (D / 128)
#define NT    2                  // N tiles (128 / 64)
#define KSPLIT 4
#define KS_LEN (D / KSPLIT)      // 1024
#define KITERS (KS_LEN / 64)     // 16

// GEMM tiling: CTA tile M=128, N=64, K-stage 64
#define PITCH   72               // smem row pitch in halves (conflict-free ldmatrix)
#define PITCHB  144              // pitch in bytes
#define A_BYTES (128 * PITCHB)   // 18432
#define B_BYTES (64 * PITCHB)    // 9216
#define STAGE_BYTES (A_BYTES + B_BYTES)   // 27648
#define NSTAGE  3
#define SMEM_TOTAL (NSTAGE * STAGE_BYTES) // 82944 B -> 2 CTAs/SM

// ---------------------------------------------------------------------------
// Static device scratch (no runtime allocation allowed)
// ---------------------------------------------------------------------------
__device__ __align__(1024) __half g_Ah[(size_t)D * D];          // W_A fp16 (32 MB)
__device__ __align__(1024) __half g_WBh[(size_t)D * C];         // W_B fp16 (4 MB)
__device__ __align__(1024) __half g_uth[(size_t)T * C];         // u^T fp16 (2 MB)
__device__ __align__(1024) float  g_v[(size_t)T * D];           // v[t][d] fp32 (32 MB)
__device__ __align__(1024) float  g_part[(size_t)KSPLIT * NCH * D]; // partials (8 MB)
__device__ __align__(1024) __half g_Y[2][(size_t)NCH * D];      // state ping-pong [n][d]

// Grid barrier state (reset by zero_kernel each replay)
__device__ unsigned          g_count;
__device__ volatile unsigned g_gen;

// ---------------------------------------------------------------------------
// PTX helpers (sm_80-era only; target PTX is compute_103 non-'a')
// ---------------------------------------------------------------------------
__device__ __forceinline__ uint32_t s2u(const void* p) {
    uint32_t a;
    asm("{ .reg .u64 t; cvta.to.shared.u64 t, %1; cvt.u32.u64 %0, t; }" : "=r"(a) : "l"(p));
    return a;
}
#define CPA16(s, g)  asm volatile("cp.async.cg.shared.global [%0], [%1], 16;" :: "r"(s), "l"(g) : "memory")
#define CPACOMMIT()  asm volatile("cp.async.commit_group;" ::: "memory")
#define CPAWAIT1()   asm volatile("cp.async.wait_group 1;" ::: "memory")

#define LDSM4(r, a)                                                             \
    asm volatile("ldmatrix.sync.aligned.m8n8.x4.shared.b16 {%0,%1,%2,%3}, [%4];" \
        : "=r"((r)[0]), "=r"((r)[1]), "=r"((r)[2]), "=r"((r)[3]) : "r"(a))

#define MMA16816(d, a, b0, b1)                                                  \
    asm volatile("mma.sync.aligned.m16n8k16.row.col.f32.f16.f16.f32 "           \
        "{%0,%1,%2,%3}, {%4,%5,%6,%7}, {%8,%9}, {%0,%1,%2,%3};"                 \
        : "+f"((d)[0]), "+f"((d)[1]), "+f"((d)[2]), "+f"((d)[3])                \
        : "r"((a)[0]), "r"((a)[1]), "r"((a)[2]), "r"((a)[3]), "r"(b0), "r"(b1))

// ---------------------------------------------------------------------------
// GEMM mainloop: acc[mi<2][ni<4][4] += Aop[128 x K] * Bop[64 x K]^T
// 256 threads / 8 warps (4m x 2n grid, 32x32 per warp). 3-stage cp.async.
// ---------------------------------------------------------------------------
__device__ __forceinline__ void load_stage(uint32_t sbase, int buf,
                                           const __half* Aop, int lda,
                                           const __half* Bop, int ldb,
                                           int kofs, int tid) {
    const uint32_t base = sbase + buf * STAGE_BYTES;
    #pragma unroll
    for (int p = 0; p < 4; p++) {                 // A: 128 rows x 64 halves
        int idx = p * 256 + tid;
        int row = idx >> 3, ch = idx & 7;
        CPA16(base + row * PITCHB + ch * 16,
              Aop + (size_t)row * lda + kofs + ch * 8);
    }
    const uint32_t bb = base + A_BYTES;
    #pragma unroll
    for (int p = 0; p < 2; p++) {                 // B: 64 rows x 64 halves
        int idx = p * 256 + tid;
        int row = idx >> 3, ch = idx & 7;
        CPA16(bb + row * PITCHB + ch * 16,
              Bop + (size_t)row * ldb + kofs + ch * 8);
    }
    CPACOMMIT();
}

__device__ __forceinline__ void gemm_main(uint32_t sbase,
                                          const __half* Aop, int lda,
                                          const __half* Bop, int ldb,
                                          int kIters, float acc[2][4][4]) {
    const int tid  = threadIdx.x;
    const int lane = tid & 31;
    const int wid  = tid >> 5;
    const int wm   = wid >> 1;   // 0..3  (32 rows each)
    const int wn   = wid & 1;    // 0..1  (32 cols each)

    load_stage(sbase, 0, Aop, lda, Bop, ldb, 0, tid);
    load_stage(sbase, 1, Aop, lda, Bop, ldb, 64, tid);

    const uint32_t aLane = (uint32_t)(((wm * 32 + (lane & 15)) * PITCH + (lane >> 4) * 8) * 2);
    const uint32_t bLane = (uint32_t)(((wn * 32 + (lane & 7) + ((lane >> 4) << 3)) * PITCH
                                       + ((lane >> 3) & 1) * 8) * 2);

    for (int it = 0; it < kIters; ++it) {
        CPAWAIT1();
        __syncthreads();
        if (it + 2 < kIters)
            load_stage(sbase, (it + 2) % NSTAGE, Aop, lda, Bop, ldb, (it + 2) * 64, tid);
        else
            CPACOMMIT();   // keep group-count invariant (tail correctness)

        const uint32_t sA = sbase + (it % NSTAGE) * STAGE_BYTES;
        const uint32_t aBase = sA + aLane;
        const uint32_t bBase = sA + A_BYTES + bLane;

        #pragma unroll
        for (int kk = 0; kk < 4; kk++) {
            uint32_t a[2][4];
            LDSM4(a[0], aBase + kk * 32);
            LDSM4(a[1], aBase + 16 * PITCHB + kk * 32);
            uint32_t b[2][4];
            LDSM4(b[0], bBase + kk * 32);
            LDSM4(b[1], bBase + 16 * PITCHB + kk * 32);
            #pragma unroll
            for (int mi = 0; mi < 2; mi++)
                #pragma unroll
                for (int ni = 0; ni < 4; ni++)
                    MMA16816(acc[mi][ni], a[mi],
                             b[ni >> 1][(ni & 1) * 2], b[ni >> 1][(ni & 1) * 2 + 1]);
        }
    }
    __syncthreads();   // all stage-smem reads done before epilogue reuse
}

// Scatter accumulators into smem as sC[m][n], pitch 69 (conflict-free col reads)
#define CPITCH 69
__device__ __forceinline__ void epilogue_to_smem(char* smem, float acc[2][4][4]) {
    float (*sC)[CPITCH] = reinterpret_cast<float (*)[CPITCH]>(smem);
    const int lane = threadIdx.x & 31;
    const int wid  = threadIdx.x >> 5;
    const int wm = wid >> 1, wn = wid & 1;
    const int r0 = wm * 32 + (lane >> 2);
    const int c0 = wn * 32 + (lane & 3) * 2;
    #pragma unroll
    for (int mi = 0; mi < 2; mi++)
        #pragma unroll
        for (int ni = 0; ni < 4; ni++) {
            int r = r0 + mi * 16, c = c0 + ni * 8;
            sC[r][c]         = acc[mi][ni][0];
            sC[r][c + 1]     = acc[mi][ni][1];
            sC[r + 8][c]     = acc[mi][ni][2];
            sC[r + 8][c + 1] = acc[mi][ni][3];
        }
    __syncthreads();
}

// ---------------------------------------------------------------------------
// Grid-wide software barrier (all 256 CTAs co-resident, 2/SM)
// ---------------------------------------------------------------------------
__device__ __forceinline__ void grid_barrier(unsigned target) {
    __threadfence();
    __syncthreads();
    if (threadIdx.x == 0) {
        unsigned old = atomicAdd(&g_count, 1u);
        if (old == (unsigned)(gridDim.x - 1)) {
            atomicExch(&g_count, 0u);
            __threadfence();
            g_gen = target;
        } else {
            while (g_gen != target) { }
            __threadfence();
        }
    }
    __syncthreads();
}

// ---------------------------------------------------------------------------
// Persistent scan kernel: all STEPS batched-recurrence steps.
// grid = 256 CTAs (32 mt x 2 nt x 4 ks), 256 threads, 2 CTAs/SM.
// ---------------------------------------------------------------------------
__global__ void __launch_bounds__(256, 2)
scan_persist_kernel(float* __restrict__ out) {
    extern __shared__ char smem[];
    const uint32_t sbase = s2u(smem);
    const int tid = threadIdx.x;
    const int mt = blockIdx.x >> 3;
    const int nt = (blockIdx.x >> 2) & 1;
    const int ks = blockIdx.x & 3;

    const __half* Aop = g_Ah + (size_t)mt * 128 * D + ks * KS_LEN;

    const int m  = tid & 127;
    const int h  = tid >> 7;
    const int mg = mt * 128 + m;

    unsigned gen = 0;

    for (int step = 0; step < STEPS; ++step) {
        const __half* ycur  = g_Y[step & 1];
        __half*       ynext = g_Y[(step & 1) ^ 1];
        const __half* Bop = ycur + (size_t)(nt * 64) * D + ks * KS_LEN;

        float acc[2][4][4];
        #pragma unroll
        for (int i = 0; i < 2; i++)
            #pragma unroll
            for (int j = 0; j < 4; j++)
                #pragma unroll
                for (int e = 0; e < 4; e++) acc[i][j][e] = 0.f;

        gemm_main(sbase, Aop, D, Bop, D, KITERS, acc);
        epilogue_to_smem(smem, acc);

        // Coalesced partial write: g_part[(ks*NCH + n)*D + m], n in CTA's 64-slice
        float (*sC)[CPITCH] = reinterpret_cast<float (*)[CPITCH]>(smem);
        #pragma unroll 4
        for (int i = 0; i < 32; i++) {
            int nl = h * 32 + i;                 // local n 0..63
            int n  = nt * 64 + nl;
            g_part[((size_t)(ks * NCH + n)) * D + mt * 128 + m] = sC[m][nl];
        }

        grid_barrier(++gen);   // all partials visible

        // Distributed combine: CTA (mt,nt,ks) owns n in [nt*64+ks*16, +16)
        {
            const float* p0 = g_part + mg;
            #pragma unroll 2
            for (int i = 0; i < 8; i++) {
                int n = nt * 64 + ks * 16 + h * 8 + i;
                float s = __ldcg(p0 + (size_t)n * D)
                        + __ldcg(p0 + (size_t)(NCH + n) * D)
                        + __ldcg(p0 + (size_t)(2 * NCH + n) * D)
                        + __ldcg(p0 + (size_t)(3 * NCH + n) * D);
                int q = n * CHK - WIN + step;
                if (q >= 0) s += g_v[(size_t)q * D + mg];
                ynext[(size_t)n * D + mg] = __float2half(s);
                if (step >= WIN) out[(size_t)q * D + mg] = s;
            }
        }

        grid_barrier(++gen);   // ynext visible before next step's B reads
    }
}

// ---------------------------------------------------------------------------
// v GEMM: g_v[t][d] = sum_c WB[d][c]*u[c][t] + bA[d] + bB[d]
// grid = 1024 CTAs (32 mt x 32 nt), 256 threads, tile 128x64xK=512
// ---------------------------------------------------------------------------
__global__ void __launch_bounds__(256, 2)
vgemm_tc_kernel(const float* __restrict__ bA, const float* __restrict__ bB) {
    extern __shared__ char smem[];
    const uint32_t sbase = s2u(smem);
    const int tid = threadIdx.x;
    const int mt = blockIdx.x & 31;
    const int nt = blockIdx.x >> 5;

    const __half* Aop = g_WBh + (size_t)mt * 128 * C;
    const __half* Bop = g_uth + (size_t)(nt * 64) * C;

    float acc[2][4][4];
    #pragma unroll
    for (int i = 0; i < 2; i++)
        #pragma unroll
        for (int j = 0; j < 4; j++)
            #pragma unroll
            for (int e = 0; e < 4; e++) acc[i][j][e] = 0.f;

    gemm_main(sbase, Aop, C, Bop, C, C / 64, acc);
    epilogue_to_smem(smem, acc);

    float (*sC)[CPITCH] = reinterpret_cast<float (*)[CPITCH]>(smem);
    const int m = tid & 127;
    const int h = tid >> 7;
    const int mg = mt * 128 + m;
    const float bias = bA[mg] + bB[mg];
    #pragma unroll 4
    for (int i = 0; i < 32; i++) {
        int nl = h * 32 + i;
        int t = nt * 64 + nl;
        g_v[(size_t)t * D + mg] = sC[m][nl] + bias;
    }
}

// ---------------------------------------------------------------------------
// Conversion / setup kernels
// ---------------------------------------------------------------------------
__global__ void convA_kernel(const float* __restrict__ WA) {
    size_t i = (size_t)blockIdx.x * blockDim.x + threadIdx.x;
    const float4* W4 = reinterpret_cast<const float4*>(WA);
    __half2* A2 = reinterpret_cast<__half2*>(g_Ah);
    float4 w = W4[i];
    A2[2 * i + 0] = __floats2half2_rn(w.x, w.y);
    A2[2 * i + 1] = __floats2half2_rn(w.z, w.w);
}

__global__ void convWB_kernel(const float* __restrict__ WB) {
    size_t i = (size_t)blockIdx.x * blockDim.x + threadIdx.x;
    const float4* W4 = reinterpret_cast<const float4*>(WB);
    __half2* A2 = reinterpret_cast<__half2*>(g_WBh);
    float4 w = W4[i];
    A2[2 * i + 0] = __floats2half2_rn(w.x, w.y);
    A2[2 * i + 1] = __floats2half2_rn(w.z, w.w);
}

// u [C][T] fp32 -> g_uth [T][C] fp16
__global__ void transu_kernel(const float* __restrict__ u) {
    __shared__ float tile[32][33];
    const int t0 = blockIdx.x * 32;
    const int c0 = blockIdx.y * 32;
    const int x = threadIdx.x, y = threadIdx.y;
    #pragma unroll
    for (int j = 0; j < 32; j += 8)
        tile[y + j][x] = u[(size_t)(c0 + y + j) * T + t0 + x];
    __syncthreads();
    #pragma unroll
    for (int j = 0; j < 32; j += 8)
        g_uth[(size_t)(t0 + y + j) * C + c0 + x] = __float2half(tile[x][y + j]);
}

// g_v[0][:] += W_A(fp32) @ x0  (exact x0 injection; runs AFTER vgemm)
__global__ void ax0_kernel(const float* __restrict__ WA, const float* __restrict__ x0) {
    const int r = blockIdx.x * 8 + (threadIdx.x >> 5);
    const int lane = threadIdx.x & 31;
    const float* row = WA + (size_t)r * D;
    float a = 0.f;
    #pragma unroll 4
    for (int k = lane; k < D; k += 32) a += row[k] * x0[k];
    #pragma unroll
    for (int off = 16; off > 0; off >>= 1) a += __shfl_down_sync(0xffffffffu, a, off);
    if (lane == 0) g_v[r] += a;
}

// Zero initial state Y[0] and barrier state (must run every replay)
__global__ void zero_kernel() {
    size_t i = (size_t)blockIdx.x * blockDim.x + threadIdx.x;
    uint32_t* y0 = reinterpret_cast<uint32_t*>(g_Y[0]);
    if (i < (size_t)NCH * D / 2) y0[i] = 0u;
    if (i == 0) { g_count = 0u; g_gen = 0u; }
}

// ---------------------------------------------------------------------------
// Entry point
// ---------------------------------------------------------------------------
extern "C" void kernel_launch(void* const* d_in, const int* in_sizes, int n_in,
                              void* d_out, int out_size)
{
    const float* x0 = (const float*)d_in[0];   // [D]
    const float* u  = (const float*)d_in[1];   // [C, T]
    const float* WA = (const float*)d_in[2];   // [D, D]
    const float* bA = (const float*)d_in[3];   // [D]
    const float* WB = (const float*)d_in[4];   // [D, C]
    const float* bB = (const float*)d_in[5];   // [D]
    float* out = (float*)d_out;                // [T, D]
    (void)in_sizes; (void)n_in; (void)out_size;

    // Opt into >48KB dynamic smem. Skip while a graph capture is active
    // (attributes were already applied during the correctness call).
    cudaStreamCaptureStatus cap = cudaStreamCaptureStatusNone;
    cudaStreamIsCapturing(0, &cap);
    if (cap == cudaStreamCaptureStatusNone) {
        cudaFuncSetAttribute(scan_persist_kernel,
                             cudaFuncAttributeMaxDynamicSharedMemorySize, SMEM_TOTAL);
        cudaFuncSetAttribute(vgemm_tc_kernel,
                             cudaFuncAttributeMaxDynamicSharedMemorySize, SMEM_TOTAL);
    }

    // Setup
    convA_kernel<<<(unsigned)((size_t)D * D / 4 / 256), 256>>>(WA);
    convWB_kernel<<<(unsigned)((size_t)D * C / 4 / 256), 256>>>(WB);
    transu_kernel<<<dim3(T / 32, C / 32), dim3(32, 8)>>>(u);
    vgemm_tc_kernel<<<MT * (T / 64), 256, SMEM_TOTAL>>>(bA, bB);
    ax0_kernel<<<D / 8, 256>>>(WA, x0);
    zero_kernel<<<1024, 256>>>();

    // All 36 batched-recurrence steps in one persistent launch
    scan_persist_kernel<<<MT * NT * KSPLIT, 256, SMEM_TOTAL>>>(out);
}

// round 10
// speedup vs baseline: 1.7170x; 1.0010x over previous
#include <cuda_runtime.h>
#include <cuda_fp16.h>
#include <cstdint>

// Problem constants
#define D 4096
#define C 512
#define T 2048

// Chunked-scan geometry
#define CHK   16                 // outputs per chunk
#define NCH   128                // T / CHK  (= GEMM N dimension)
#define WIN   20                 // warmup window (0.64^21 ~ 8.6e-5 truncation)
#define STEPS (WIN + CHK)        // 36 sequential batched steps
#define MT    32                 // M tiles (D / 128)
#define NT    2                  // N tiles (128 / 64)
#define KSPLIT 4
#define KS_LEN (D / KSPLIT)      // 1024
#define KITERS (KS_LEN / 64)     // 16

// GEMM tiling: CTA tile M=128, N=64, K-stage 64
#define PITCH   72               // smem row pitch in halves (conflict-free ldmatrix)
#define PITCHB  144              // pitch in bytes
#define A_BYTES (128 * PITCHB)   // 18432
#define B_BYTES (64 * PITCHB)    // 9216
#define STAGE_BYTES (A_BYTES + B_BYTES)   // 27648
#define NSTAGE  3
#define SMEM_TOTAL (NSTAGE * STAGE_BYTES) // 82944 B -> 2 CTAs/SM
// Epilogue sC lives in stage1+stage2 region (stage0 reserved for A0 prefetch)
#define CPITCH 69                         // 128 x 69 floats = 35328 B < 2*STAGE_BYTES

// ---------------------------------------------------------------------------
// Static device scratch (no runtime allocation allowed)
// ---------------------------------------------------------------------------
__device__ __align__(1024) __half g_Ah[(size_t)D * D];          // W_A fp16 (32 MB)
__device__ __align__(1024) __half g_WBh[(size_t)D * C];         // W_B fp16 (4 MB)
__device__ __align__(1024) __half g_uth[(size_t)T * C];         // u^T fp16 (2 MB)
__device__ __align__(1024) float  g_v[(size_t)T * D];           // v[t][d] fp32 (32 MB)
__device__ __align__(1024) float  g_part[(size_t)KSPLIT * NCH * D]; // partials (8 MB)
__device__ __align__(1024) __half g_Y[2][(size_t)NCH * D];      // state ping-pong [n][d]

// Grid barrier state (reset by zero_kernel each replay)
__device__ unsigned          g_count;
__device__ volatile unsigned g_gen;

// ---------------------------------------------------------------------------
// PTX helpers (sm_80-era only; target PTX is compute_103 non-'a')
// ---------------------------------------------------------------------------
__device__ __forceinline__ uint32_t s2u(const void* p) {
    uint32_t a;
    asm("{ .reg .u64 t; cvta.to.shared.u64 t, %1; cvt.u32.u64 %0, t; }" : "=r"(a) : "l"(p));
    return a;
}
#define CPA16(s, g)  asm volatile("cp.async.cg.shared.global [%0], [%1], 16;" :: "r"(s), "l"(g) : "memory")
#define CPACOMMIT()  asm volatile("cp.async.commit_group;" ::: "memory")
#define CPAWAIT1()   asm volatile("cp.async.wait_group 1;" ::: "memory")
#define CPAWAIT2()   asm volatile("cp.async.wait_group 2;" ::: "memory")

#define LDSM4(r, a)                                                             \
    asm volatile("ldmatrix.sync.aligned.m8n8.x4.shared.b16 {%0,%1,%2,%3}, [%4];" \
        : "=r"((r)[0]), "=r"((r)[1]), "=r"((r)[2]), "=r"((r)[3]) : "r"(a))

#define MMA16816(d, a, b0, b1)                                                  \
    asm volatile("mma.sync.aligned.m16n8k16.row.col.f32.f16.f16.f32 "           \
        "{%0,%1,%2,%3}, {%4,%5,%6,%7}, {%8,%9}, {%0,%1,%2,%3};"                 \
        : "+f"((d)[0]), "+f"((d)[1]), "+f"((d)[2]), "+f"((d)[3])                \
        : "r"((a)[0]), "r"((a)[1]), "r"((a)[2]), "r"((a)[3]), "r"(b0), "r"(b1))

// ---------------------------------------------------------------------------
// Stage loaders. A and B are SEPARATE cp.async groups (order: A_s then B_s).
// ---------------------------------------------------------------------------
__device__ __forceinline__ void load_A(uint32_t sbase, int buf,
                                       const __half* Aop, int lda,
                                       int kofs, int tid) {
    const uint32_t base = sbase + buf * STAGE_BYTES;
    #pragma unroll
    for (int p = 0; p < 4; p++) {                 // A: 128 rows x 64 halves
        int idx = p * 256 + tid;
        int row = idx >> 3, ch = idx & 7;
        CPA16(base + row * PITCHB + ch * 16,
              Aop + (size_t)row * lda + kofs + ch * 8);
    }
    CPACOMMIT();
}

__device__ __forceinline__ void load_B(uint32_t sbase, int buf,
                                       const __half* Bop, int ldb,
                                       int kofs, int tid) {
    const uint32_t base = sbase + buf * STAGE_BYTES + A_BYTES;
    #pragma unroll
    for (int p = 0; p < 2; p++) {                 // B: 64 rows x 64 halves
        int idx = p * 256 + tid;
        int row = idx >> 3, ch = idx & 7;
        CPA16(base + row * PITCHB + ch * 16,
              Bop + (size_t)row * ldb + kofs + ch * 8);
    }
    CPACOMMIT();
}

// ---------------------------------------------------------------------------
// GEMM mainloop: acc[mi<2][ni<4][4] += Aop[128 x K] * Bop[64 x K]^T
// 256 threads / 8 warps (4m x 2n grid, 32x32 per warp). 3-stage cp.async with
// split A/B groups. PRECONDITION: caller has already committed the A group for
// stage 0 (cross-step prefetch). Fragments are double-buffered across kk.
// ---------------------------------------------------------------------------
__device__ __forceinline__ void gemm_main(uint32_t sbase,
                                          const __half* Aop, int lda,
                                          const __half* Bop, int ldb,
                                          int kIters, float acc[2][4][4]) {
    const int tid  = threadIdx.x;
    const int lane = tid & 31;
    const int wid  = tid >> 5;
    const int wm   = wid >> 1;   // 0..3  (32 rows each)
    const int wn   = wid & 1;    // 0..1  (32 cols each)

    // Group sequence: [A0 caller] [A1] [B0] [B1], then per iter [A_s][B_s]
    load_A(sbase, 1, Aop, lda, 64, tid);
    load_B(sbase, 0, Bop, ldb, 0, tid);
    load_B(sbase, 1, Bop, ldb, 64, tid);

    const uint32_t aLane = (uint32_t)(((wm * 32 + (lane & 15)) * PITCH + (lane >> 4) * 8) * 2);
    const uint32_t bLane = (uint32_t)(((wn * 32 + (lane & 7) + ((lane >> 4) << 3)) * PITCH
                                       + ((lane >> 3) & 1) * 8) * 2);

    for (int it = 0; it < kIters; ++it) {
        // iter0: first 3 groups (A0,A1,B0) must retire -> wait_group 1 (4 issued)
        // it>=1: need first 2it+2 of 4+2it issued -> wait_group 2
        if (it == 0) CPAWAIT1(); else CPAWAIT2();
        __syncthreads();
        if (it + 2 < kIters) {
            load_A(sbase, (it + 2) % NSTAGE, Aop, lda, (it + 2) * 64, tid);
            load_B(sbase, (it + 2) % NSTAGE, Bop, ldb, (it + 2) * 64, tid);
        } else {
            CPACOMMIT(); CPACOMMIT();   // keep group-count invariant
        }

        const uint32_t sA = sbase + (it % NSTAGE) * STAGE_BYTES;
        const uint32_t aBase = sA + aLane;
        const uint32_t bBase = sA + A_BYTES + bLane;

        // Double-buffered fragments across kk
        uint32_t af[2][2][4], bf[2][2][4];
        LDSM4(af[0][0], aBase);
        LDSM4(af[0][1], aBase + 16 * PITCHB);
        LDSM4(bf[0][0], bBase);
        LDSM4(bf[0][1], bBase + 16 * PITCHB);

        #pragma unroll
        for (int kk = 0; kk < 4; kk++) {
            const int cur = kk & 1, nxt = cur ^ 1;
            if (kk < 3) {
                LDSM4(af[nxt][0], aBase + (kk + 1) * 32);
                LDSM4(af[nxt][1], aBase + 16 * PITCHB + (kk + 1) * 32);
                LDSM4(bf[nxt][0], bBase + (kk + 1) * 32);
                LDSM4(bf[nxt][1], bBase + 16 * PITCHB + (kk + 1) * 32);
            }
            #pragma unroll
            for (int mi = 0; mi < 2; mi++)
                #pragma unroll
                for (int ni = 0; ni < 4; ni++)
                    MMA16816(acc[mi][ni], af[cur][mi],
                             bf[cur][ni >> 1][(ni & 1) * 2],
                             bf[cur][ni >> 1][(ni & 1) * 2 + 1]);
        }
    }
    __syncthreads();   // all stage-smem reads done before epilogue/prefetch reuse
}

// Scatter accumulators into smem sC[m][n] located at smem + STAGE_BYTES
// (stage1+stage2 region; stage0 stays free for the cross-step A0 prefetch).
__device__ __forceinline__ void epilogue_to_smem(char* smem, float acc[2][4][4]) {
    float (*sC)[CPITCH] = reinterpret_cast<float (*)[CPITCH]>(smem + STAGE_BYTES);
    const int lane = threadIdx.x & 31;
    const int wid  = threadIdx.x >> 5;
    const int wm = wid >> 1, wn = wid & 1;
    const int r0 = wm * 32 + (lane >> 2);
    const int c0 = wn * 32 + (lane & 3) * 2;
    #pragma unroll
    for (int mi = 0; mi < 2; mi++)
        #pragma unroll
        for (int ni = 0; ni < 4; ni++) {
            int r = r0 + mi * 16, c = c0 + ni * 8;
            sC[r][c]         = acc[mi][ni][0];
            sC[r][c + 1]     = acc[mi][ni][1];
            sC[r + 8][c]     = acc[mi][ni][2];
            sC[r + 8][c + 1] = acc[mi][ni][3];
        }
    __syncthreads();
}

// ---------------------------------------------------------------------------
// Grid-wide software barrier (all 256 CTAs co-resident, 2/SM)
// ---------------------------------------------------------------------------
__device__ __forceinline__ void grid_barrier(unsigned target) {
    __threadfence();
    __syncthreads();
    if (threadIdx.x == 0) {
        unsigned old = atomicAdd(&g_count, 1u);
        if (old == (unsigned)(gridDim.x - 1)) {
            atomicExch(&g_count, 0u);
            __threadfence();
            g_gen = target;
        } else {
            while (g_gen != target) { }
            __threadfence();
        }
    }
    __syncthreads();
}

// ---------------------------------------------------------------------------
// Persistent scan kernel: all STEPS batched-recurrence steps.
// grid = 256 CTAs (32 mt x 2 nt x 4 ks), 256 threads, 2 CTAs/SM.
// ---------------------------------------------------------------------------
__global__ void __launch_bounds__(256, 2)
scan_persist_kernel(float* __restrict__ out) {
    extern __shared__ char smem[];
    const uint32_t sbase = s2u(smem);
    const int tid = threadIdx.x;
    const int mt = blockIdx.x >> 3;
    const int nt = (blockIdx.x >> 2) & 1;
    const int ks = blockIdx.x & 3;

    const __half* Aop = g_Ah + (size_t)mt * 128 * D + ks * KS_LEN;

    const int m  = tid & 127;
    const int h  = tid >> 7;
    const int mg = mt * 128 + m;

    unsigned gen = 0;

    // A-stage0 prefetch for step 0 (constant across steps)
    load_A(sbase, 0, Aop, D, 0, tid);

    for (int step = 0; step < STEPS; ++step) {
        const __half* ycur  = g_Y[step & 1];
        __half*       ynext = g_Y[(step & 1) ^ 1];
        const __half* Bop = ycur + (size_t)(nt * 64) * D + ks * KS_LEN;

        float acc[2][4][4];
        #pragma unroll
        for (int i = 0; i < 2; i++)
            #pragma unroll
            for (int j = 0; j < 4; j++)
                #pragma unroll
                for (int e = 0; e < 4; e++) acc[i][j][e] = 0.f;

        gemm_main(sbase, Aop, D, Bop, D, KITERS, acc);
        epilogue_to_smem(smem, acc);

        // Prefetch next step's A-stage0 (constant data, stage0 buffer is free;
        // overlaps the partial stores, both barriers, and the combine)
        load_A(sbase, 0, Aop, D, 0, tid);

        // Coalesced partial write. Skip the 16 columns this CTA combines
        // locally from sC (nobody else reads them).
        float (*sC)[CPITCH] = reinterpret_cast<float (*)[CPITCH]>(smem + STAGE_BYTES);
        #pragma unroll 4
        for (int i = 0; i < 32; i++) {
            int nl = h * 32 + i;                 // local n 0..63
            if ((nl >> 4) != ks) {
                int n = nt * 64 + nl;
                g_part[((size_t)(ks * NCH + n)) * D + mt * 128 + m] = sC[m][nl];
            }
        }

        grid_barrier(++gen);   // all partials visible

        // Distributed combine: CTA (mt,nt,ks) owns n in [nt*64+ks*16, +16).
        // Own K-partial comes from local sC; 3 foreign from L2.
        {
            const float* p0 = g_part + mg;
            #pragma unroll 2
            for (int i = 0; i < 8; i++) {
                int nl = ks * 16 + h * 8 + i;
                int n  = nt * 64 + nl;
                float s = 0.f;
                #pragma unroll
                for (int kk2 = 0; kk2 < 4; kk2++) {
                    float val = (kk2 == ks) ? sC[m][nl]
                              : __ldcg(p0 + (size_t)(kk2 * NCH + n) * D);
                    s += val;
                }
                int q = n * CHK - WIN + step;
                if (q >= 0) s += g_v[(size_t)q * D + mg];
                ynext[(size_t)n * D + mg] = __float2half(s);
                if (step >= WIN) out[(size_t)q * D + mg] = s;
            }
        }

        grid_barrier(++gen);   // ynext visible before next step's B reads
    }
}

// ---------------------------------------------------------------------------
// v GEMM: g_v[t][d] = sum_c WB[d][c]*u[c][t] + bA[d] + bB[d]
// grid = 1024 CTAs (32 mt x 32 nt), 256 threads, tile 128x64xK=512
// ---------------------------------------------------------------------------
__global__ void __launch_bounds__(256, 2)
vgemm_tc_kernel(const float* __restrict__ bA, const float* __restrict__ bB) {
    extern __shared__ char smem[];
    const uint32_t sbase = s2u(smem);
    const int tid = threadIdx.x;
    const int mt = blockIdx.x & 31;
    const int nt = blockIdx.x >> 5;

    const __half* Aop = g_WBh + (size_t)mt * 128 * C;
    const __half* Bop = g_uth + (size_t)(nt * 64) * C;

    float acc[2][4][4];
    #pragma unroll
    for (int i = 0; i < 2; i++)
        #pragma unroll
        for (int j = 0; j < 4; j++)
            #pragma unroll
            for (int e = 0; e < 4; e++) acc[i][j][e] = 0.f;

    load_A(sbase, 0, Aop, C, 0, tid);   // satisfy gemm_main's A0 precondition
    gemm_main(sbase, Aop, C, Bop, C, C / 64, acc);
    epilogue_to_smem(smem, acc);

    float (*sC)[CPITCH] = reinterpret_cast<float (*)[CPITCH]>(smem + STAGE_BYTES);
    const int m = tid & 127;
    const int h = tid >> 7;
    const int mg = mt * 128 + m;
    const float bias = bA[mg] + bB[mg];
    #pragma unroll 4
    for (int i = 0; i < 32; i++) {
        int nl = h * 32 + i;
        int t = nt * 64 + nl;
        g_v[(size_t)t * D + mg] = sC[m][nl] + bias;
    }
}

// ---------------------------------------------------------------------------
// Conversion / setup kernels
// ---------------------------------------------------------------------------
__global__ void convA_kernel(const float* __restrict__ WA) {
    size_t i = (size_t)blockIdx.x * blockDim.x + threadIdx.x;
    const float4* W4 = reinterpret_cast<const float4*>(WA);
    __half2* A2 = reinterpret_cast<__half2*>(g_Ah);
    float4 w = W4[i];
    A2[2 * i + 0] = __floats2half2_rn(w.x, w.y);
    A2[2 * i + 1] = __floats2half2_rn(w.z, w.w);
}

__global__ void convWB_kernel(const float* __restrict__ WB) {
    size_t i = (size_t)blockIdx.x * blockDim.x + threadIdx.x;
    const float4* W4 = reinterpret_cast<const float4*>(WB);
    __half2* A2 = reinterpret_cast<__half2*>(g_WBh);
    float4 w = W4[i];
    A2[2 * i + 0] = __floats2half2_rn(w.x, w.y);
    A2[2 * i + 1] = __floats2half2_rn(w.z, w.w);
}

// u [C][T] fp32 -> g_uth [T][C] fp16
__global__ void transu_kernel(const float* __restrict__ u) {
    __shared__ float tile[32][33];
    const int t0 = blockIdx.x * 32;
    const int c0 = blockIdx.y * 32;
    const int x = threadIdx.x, y = threadIdx.y;
    #pragma unroll
    for (int j = 0; j < 32; j += 8)
        tile[y + j][x] = u[(size_t)(c0 + y + j) * T + t0 + x];
    __syncthreads();
    #pragma unroll
    for (int j = 0; j < 32; j += 8)
        g_uth[(size_t)(t0 + y + j) * C + c0 + x] = __float2half(tile[x][y + j]);
}

// g_v[0][:] += W_A(fp32) @ x0  (exact x0 injection; runs AFTER vgemm)
__global__ void ax0_kernel(const float* __restrict__ WA, const float* __restrict__ x0) {
    const int r = blockIdx.x * 8 + (threadIdx.x >> 5);
    const int lane = threadIdx.x & 31;
    const float* row = WA + (size_t)r * D;
    float a = 0.f;
    #pragma unroll 4
    for (int k = lane; k < D; k += 32) a += row[k] * x0[k];
    #pragma unroll
    for (int off = 16; off > 0; off >>= 1) a += __shfl_down_sync(0xffffffffu, a, off);
    if (lane == 0) g_v[r] += a;
}

// Zero initial state Y[0] and barrier state (must run every replay)
__global__ void zero_kernel() {
    size_t i = (size_t)blockIdx.x * blockDim.x + threadIdx.x;
    uint32_t* y0 = reinterpret_cast<uint32_t*>(g_Y[0]);
    if (i < (size_t)NCH * D / 2) y0[i] = 0u;
    if (i == 0) { g_count = 0u; g_gen = 0u; }
}

// ---------------------------------------------------------------------------
// Entry point
// ---------------------------------------------------------------------------
extern "C" void kernel_launch(void* const* d_in, const int* in_sizes, int n_in,
                              void* d_out, int out_size)
{
    const float* x0 = (const float*)d_in[0];   // [D]
    const float* u  = (const float*)d_in[1];   // [C, T]
    const float* WA = (const float*)d_in[2];   // [D, D]
    const float* bA = (const float*)d_in[3];   // [D]
    const float* WB = (const float*)d_in[4];   // [D, C]
    const float* bB = (const float*)d_in[5];   // [D]
    float* out = (float*)d_out;                // [T, D]
    (void)in_sizes; (void)n_in; (void)out_size;

    // Opt into >48KB dynamic smem. Skip while a graph capture is active
    // (attributes were already applied during the correctness call).
    cudaStreamCaptureStatus cap = cudaStreamCaptureStatusNone;
    cudaStreamIsCapturing(0, &cap);
    if (cap == cudaStreamCaptureStatusNone) {
        cudaFuncSetAttribute(scan_persist_kernel,
                             cudaFuncAttributeMaxDynamicSharedMemorySize, SMEM_TOTAL);
        cudaFuncSetAttribute(vgemm_tc_kernel,
                             cudaFuncAttributeMaxDynamicSharedMemorySize, SMEM_TOTAL);
    }

    // Setup
    convA_kernel<<<(unsigned)((size_t)D * D / 4 / 256), 256>>>(WA);
    convWB_kernel<<<(unsigned)((size_t)D * C / 4 / 256), 256>>>(WB);
    transu_kernel<<<dim3(T / 32, C / 32), dim3(32, 8)>>>(u);
    vgemm_tc_kernel<<<MT * (T / 64), 256, SMEM_TOTAL>>>(bA, bB);
    ax0_kernel<<<D / 8, 256>>>(WA, x0);
    zero_kernel<<<1024, 256>>>();

    // All 36 batched-recurrence steps in one persistent launch
    scan_persist_kernel<<<MT * NT * KSPLIT, 256, SMEM_TOTAL>>>(out);
}

// round 11
// speedup vs baseline: 2.0411x; 1.1888x over previous
#include <cuda_runtime.h>
#include <cuda_fp16.h>
#include <cstdint>

// Problem constants
#define D 4096
#define C 512
#define T 2048

// Chunked-scan geometry
#define CHK   32                 // outputs per chunk
#define NCH   64                 // T / CHK  (= GEMM N dimension)
#define WIN   18                 // warmup window (0.64^19 ~ 2.1e-4 truncation)
#define STEPS (WIN + CHK)        // 50 sequential batched steps
#define MT    32                 // M tiles (D / 128)
#define KSPLIT 8
#define KS_LEN (D / KSPLIT)      // 512
#define KITERS (KS_LEN / 64)     // 8

// GEMM tiling: CTA tile M=128, N=64, K-stage 64
#define PITCH   72               // smem row pitch in halves (conflict-free ldmatrix)
#define PITCHB  144              // pitch in bytes
#define A_BYTES (128 * PITCHB)   // 18432
#define B_BYTES (64 * PITCHB)    // 9216
#define STAGE_BYTES (A_BYTES + B_BYTES)   // 27648
#define NSTAGE  3
#define SMEM_TOTAL (NSTAGE * STAGE_BYTES) // 82944 B -> 2 CTAs/SM

// ---------------------------------------------------------------------------
// Static device scratch (no runtime allocation allowed)
// ---------------------------------------------------------------------------
__device__ __align__(1024) __half g_Ah[(size_t)D * D];          // W_A fp16 (32 MB)
__device__ __align__(1024) __half g_WBh[(size_t)D * C];         // W_B fp16 (4 MB)
__device__ __align__(1024) __half g_uth[(size_t)T * C];         // u^T fp16 (2 MB)
__device__ __align__(1024) float  g_v[(size_t)T * D];           // v[t][d] fp32 (32 MB)
__device__ __align__(1024) float  g_part[(size_t)KSPLIT * NCH * D]; // partials (8 MB)
__device__ __align__(1024) __half g_Y[2][(size_t)NCH * D];      // state ping-pong [n][d]

// Grid barrier state (reset by zero_kernel each replay)
__device__ unsigned          g_count;
__device__ volatile unsigned g_gen;

// ---------------------------------------------------------------------------
// PTX helpers (sm_80-era only; target PTX is compute_103 non-'a')
// ---------------------------------------------------------------------------
__device__ __forceinline__ uint32_t s2u(const void* p) {
    uint32_t a;
    asm("{ .reg .u64 t; cvta.to.shared.u64 t, %1; cvt.u32.u64 %0, t; }" : "=r"(a) : "l"(p));
    return a;
}
#define CPA16(s, g)  asm volatile("cp.async.cg.shared.global [%0], [%1], 16;" :: "r"(s), "l"(g) : "memory")
#define CPACOMMIT()  asm volatile("cp.async.commit_group;" ::: "memory")
#define CPAWAIT1()   asm volatile("cp.async.wait_group 1;" ::: "memory")
#define CPAWAIT2()   asm volatile("cp.async.wait_group 2;" ::: "memory")

#define LDSM4(r, a)                                                             \
    asm volatile("ldmatrix.sync.aligned.m8n8.x4.shared.b16 {%0,%1,%2,%3}, [%4];" \
        : "=r"((r)[0]), "=r"((r)[1]), "=r"((r)[2]), "=r"((r)[3]) : "r"(a))

#define MMA16816(d, a, b0, b1)                                                  \
    asm volatile("mma.sync.aligned.m16n8k16.row.col.f32.f16.f16.f32 "           \
        "{%0,%1,%2,%3}, {%4,%5,%6,%7}, {%8,%9}, {%0,%1,%2,%3};"                 \
        : "+f"((d)[0]), "+f"((d)[1]), "+f"((d)[2]), "+f"((d)[3])                \
        : "r"((a)[0]), "r"((a)[1]), "r"((a)[2]), "r"((a)[3]), "r"(b0), "r"(b1))

// ---------------------------------------------------------------------------
// Stage loaders. A and B are SEPARATE cp.async groups (order: A_s then B_s).
// ---------------------------------------------------------------------------
__device__ __forceinline__ void load_A(uint32_t sbase, int buf,
                                       const __half* Aop, int lda,
                                       int kofs, int tid) {
    const uint32_t base = sbase + buf * STAGE_BYTES;
    #pragma unroll
    for (int p = 0; p < 4; p++) {                 // A: 128 rows x 64 halves
        int idx = p * 256 + tid;
        int row = idx >> 3, ch = idx & 7;
        CPA16(base + row * PITCHB + ch * 16,
              Aop + (size_t)row * lda + kofs + ch * 8);
    }
    CPACOMMIT();
}

__device__ __forceinline__ void load_B(uint32_t sbase, int buf,
                                       const __half* Bop, int ldb,
                                       int kofs, int tid) {
    const uint32_t base = sbase + buf * STAGE_BYTES + A_BYTES;
    #pragma unroll
    for (int p = 0; p < 2; p++) {                 // B: 64 rows x 64 halves
        int idx = p * 256 + tid;
        int row = idx >> 3, ch = idx & 7;
        CPA16(base + row * PITCHB + ch * 16,
              Bop + (size_t)row * ldb + kofs + ch * 8);
    }
    CPACOMMIT();
}

// ---------------------------------------------------------------------------
// GEMM mainloop: acc[mi<2][ni<4][4] += Aop[128 x K] * Bop[64 x K]^T
// 256 threads / 8 warps (4m x 2n grid, 32x32 per warp). 3-stage cp.async with
// split A/B groups. PRECONDITION: caller has already committed the A group for
// stage 0 (cross-step prefetch).
// ---------------------------------------------------------------------------
__device__ __forceinline__ void gemm_main(uint32_t sbase,
                                          const __half* Aop, int lda,
                                          const __half* Bop, int ldb,
                                          int kIters, float acc[2][4][4]) {
    const int tid  = threadIdx.x;
    const int lane = tid & 31;
    const int wid  = tid >> 5;
    const int wm   = wid >> 1;   // 0..3  (32 rows each)
    const int wn   = wid & 1;    // 0..1  (32 cols each)

    // Group sequence: [A0 caller] [A1] [B0] [B1], then per iter [A_s][B_s]
    load_A(sbase, 1, Aop, lda, 64, tid);
    load_B(sbase, 0, Bop, ldb, 0, tid);
    load_B(sbase, 1, Bop, ldb, 64, tid);

    const uint32_t aLane = (uint32_t)(((wm * 32 + (lane & 15)) * PITCH + (lane >> 4) * 8) * 2);
    const uint32_t bLane = (uint32_t)(((wn * 32 + (lane & 7) + ((lane >> 4) << 3)) * PITCH
                                       + ((lane >> 3) & 1) * 8) * 2);

    for (int it = 0; it < kIters; ++it) {
        // iter0: A0,A1,B0 must retire -> wait_group 1 (of 4 issued)
        // it>=1: need first 2it+2 of 4+2it issued -> wait_group 2
        if (it == 0) CPAWAIT1(); else CPAWAIT2();
        __syncthreads();
        if (it + 2 < kIters) {
            load_A(sbase, (it + 2) % NSTAGE, Aop, lda, (it + 2) * 64, tid);
            load_B(sbase, (it + 2) % NSTAGE, Bop, ldb, (it + 2) * 64, tid);
        } else {
            CPACOMMIT(); CPACOMMIT();   // keep group-count invariant
        }

        const uint32_t sA = sbase + (it % NSTAGE) * STAGE_BYTES;
        const uint32_t aBase = sA + aLane;
        const uint32_t bBase = sA + A_BYTES + bLane;

        // Double-buffered fragments across kk
        uint32_t af[2][2][4], bf[2][2][4];
        LDSM4(af[0][0], aBase);
        LDSM4(af[0][1], aBase + 16 * PITCHB);
        LDSM4(bf[0][0], bBase);
        LDSM4(bf[0][1], bBase + 16 * PITCHB);

        #pragma unroll
        for (int kk = 0; kk < 4; kk++) {
            const int cur = kk & 1, nxt = cur ^ 1;
            if (kk < 3) {
                LDSM4(af[nxt][0], aBase + (kk + 1) * 32);
                LDSM4(af[nxt][1], aBase + 16 * PITCHB + (kk + 1) * 32);
                LDSM4(bf[nxt][0], bBase + (kk + 1) * 32);
                LDSM4(bf[nxt][1], bBase + 16 * PITCHB + (kk + 1) * 32);
            }
            #pragma unroll
            for (int mi = 0; mi < 2; mi++)
                #pragma unroll
                for (int ni = 0; ni < 4; ni++)
                    MMA16816(acc[mi][ni], af[cur][mi],
                             bf[cur][ni >> 1][(ni & 1) * 2],
                             bf[cur][ni >> 1][(ni & 1) * 2 + 1]);
        }
    }
    __syncthreads();   // all stage-smem reads done before prefetch reuse
}

// ---------------------------------------------------------------------------
// Direct register->gmem epilogue: write acc to rows[n] x cols[m] array
// dst[(rowBase + n) * D + mBase + m]. Quarter-warp writes 32B sectors.
// ---------------------------------------------------------------------------
__device__ __forceinline__ void store_acc(float* dst, size_t rowBase, int mBase,
                                          float acc[2][4][4]) {
    const int lane = threadIdx.x & 31;
    const int wid  = threadIdx.x >> 5;
    const int wm = wid >> 1, wn = wid & 1;
    const int r0 = wm * 32 + (lane >> 2);       // m within tile
    const int c0 = wn * 32 + (lane & 3) * 2;    // n within tile
    #pragma unroll
    for (int mi = 0; mi < 2; mi++)
        #pragma unroll
        for (int ni = 0; ni < 4; ni++) {
            int m = mBase + r0 + mi * 16;
            int n = c0 + ni * 8;
            dst[(rowBase + n) * D + m]           = acc[mi][ni][0];
            dst[(rowBase + n + 1) * D + m]       = acc[mi][ni][1];
            dst[(rowBase + n) * D + m + 8]       = acc[mi][ni][2];
            dst[(rowBase + n + 1) * D + m + 8]   = acc[mi][ni][3];
        }
}

// ---------------------------------------------------------------------------
// Grid-wide software barrier (all 256 CTAs co-resident, 2/SM)
// ---------------------------------------------------------------------------
__device__ __forceinline__ void grid_barrier(unsigned target) {
    __threadfence();
    __syncthreads();
    if (threadIdx.x == 0) {
        unsigned old = atomicAdd(&g_count, 1u);
        if (old == (unsigned)(gridDim.x - 1)) {
            atomicExch(&g_count, 0u);
            __threadfence();
            g_gen = target;
        } else {
            while (g_gen != target) { }
            __threadfence();
        }
    }
    __syncthreads();
}

// ---------------------------------------------------------------------------
// Persistent scan kernel: all STEPS batched-recurrence steps.
// grid = 256 CTAs (32 mt x 8 ks), 256 threads, 2 CTAs/SM.
// ---------------------------------------------------------------------------
__global__ void __launch_bounds__(256, 2)
scan_persist_kernel(float* __restrict__ out) {
    extern __shared__ char smem[];
    const uint32_t sbase = s2u(smem);
    const int tid = threadIdx.x;
    const int mt = blockIdx.x >> 3;
    const int ks = blockIdx.x & 7;

    const __half* Aop = g_Ah + (size_t)mt * 128 * D + ks * KS_LEN;

    const int m  = tid & 127;
    const int h  = tid >> 7;
    const int mg = mt * 128 + m;

    unsigned gen = 0;

    // A-stage0 prefetch for step 0 (A constant across steps)
    load_A(sbase, 0, Aop, D, 0, tid);

    for (int step = 0; step < STEPS; ++step) {
        const __half* ycur  = g_Y[step & 1];
        __half*       ynext = g_Y[(step & 1) ^ 1];
        const __half* Bop = ycur + ks * KS_LEN;

        float acc[2][4][4];
        #pragma unroll
        for (int i = 0; i < 2; i++)
            #pragma unroll
            for (int j = 0; j < 4; j++)
                #pragma unroll
                for (int e = 0; e < 4; e++) acc[i][j][e] = 0.f;

        gemm_main(sbase, Aop, D, Bop, D, KITERS, acc);

        // Prefetch next step's A-stage0 (overlaps stores + barriers + combine)
        if (step + 1 < STEPS) load_A(sbase, 0, Aop, D, 0, tid);

        // Direct partial store: g_part[(ks*NCH + n)*D + (mt*128 + m)]
        store_acc(g_part, (size_t)ks * NCH, mt * 128, acc);

        grid_barrier(++gen);   // all partials visible

        // Distributed combine: CTA (mt,ks) owns n in [ks*8, ks*8+8),
        // m in its mt slice. Fixed-order 8-way sum (deterministic).
        {
            const float* p0 = g_part + mg;
            #pragma unroll
            for (int i = 0; i < 4; i++) {
                int n = ks * 8 + h * 4 + i;
                float s = 0.f;
                #pragma unroll
                for (int kk = 0; kk < KSPLIT; kk++)
                    s += __ldcg(p0 + (size_t)(kk * NCH + n) * D);
                int q = n * CHK - WIN + step;
                if (q >= 0) s += g_v[(size_t)q * D + mg];
                ynext[(size_t)n * D + mg] = __float2half(s);
                if (step >= WIN) out[(size_t)q * D + mg] = s;
            }
        }

        grid_barrier(++gen);   // ynext visible before next step's B reads
    }
}

// ---------------------------------------------------------------------------
// v GEMM: g_v[t][d] = sum_c WB[d][c]*u[c][t] + bA[d] + bB[d]
// grid = 1024 CTAs (32 mt x 32 nt), 256 threads, tile 128x64xK=512
// ---------------------------------------------------------------------------
__global__ void __launch_bounds__(256, 2)
vgemm_tc_kernel(const float* __restrict__ bA, const float* __restrict__ bB) {
    extern __shared__ char smem[];
    const uint32_t sbase = s2u(smem);
    const int tid = threadIdx.x;
    const int mt = blockIdx.x & 31;
    const int nt = blockIdx.x >> 5;

    const __half* Aop = g_WBh + (size_t)mt * 128 * C;
    const __half* Bop = g_uth + (size_t)(nt * 64) * C;

    float acc[2][4][4];
    #pragma unroll
    for (int i = 0; i < 2; i++)
        #pragma unroll
        for (int j = 0; j < 4; j++)
            #pragma unroll
            for (int e = 0; e < 4; e++) acc[i][j][e] = 0.f;

    load_A(sbase, 0, Aop, C, 0, tid);   // satisfy gemm_main's A0 precondition
    gemm_main(sbase, Aop, C, Bop, C, C / 64, acc);

    // Add bias into accumulators, then direct store to g_v[t][d]
    {
        const int lane = tid & 31;
        const int wid  = tid >> 5;
        const int wm = wid >> 1;
        const int r0 = wm * 32 + (lane >> 2);
        #pragma unroll
        for (int mi = 0; mi < 2; mi++) {
            int d0 = mt * 128 + r0 + mi * 16;
            float bias0 = bA[d0] + bB[d0];
            float bias8 = bA[d0 + 8] + bB[d0 + 8];
            #pragma unroll
            for (int ni = 0; ni < 4; ni++) {
                acc[mi][ni][0] += bias0;
                acc[mi][ni][1] += bias0;
                acc[mi][ni][2] += bias8;
                acc[mi][ni][3] += bias8;
            }
        }
    }
    store_acc(g_v, (size_t)nt * 64, mt * 128, acc);
}

// ---------------------------------------------------------------------------
// Conversion / setup kernels
// ---------------------------------------------------------------------------
__global__ void convA_kernel(const float* __restrict__ WA) {
    size_t i = (size_t)blockIdx.x * blockDim.x + threadIdx.x;
    const float4* W4 = reinterpret_cast<const float4*>(WA);
    __half2* A2 = reinterpret_cast<__half2*>(g_Ah);
    float4 w = W4[i];
    A2[2 * i + 0] = __floats2half2_rn(w.x, w.y);
    A2[2 * i + 1] = __floats2half2_rn(w.z, w.w);
}

__global__ void convWB_kernel(const float* __restrict__ WB) {
    size_t i = (size_t)blockIdx.x * blockDim.x + threadIdx.x;
    const float4* W4 = reinterpret_cast<const float4*>(WB);
    __half2* A2 = reinterpret_cast<__half2*>(g_WBh);
    float4 w = W4[i];
    A2[2 * i + 0] = __floats2half2_rn(w.x, w.y);
    A2[2 * i + 1] = __floats2half2_rn(w.z, w.w);
}

// u [C][T] fp32 -> g_uth [T][C] fp16
__global__ void transu_kernel(const float* __restrict__ u) {
    __shared__ float tile[32][33];
    const int t0 = blockIdx.x * 32;
    const int c0 = blockIdx.y * 32;
    const int x = threadIdx.x, y = threadIdx.y;
    #pragma unroll
    for (int j = 0; j < 32; j += 8)
        tile[y + j][x] = u[(size_t)(c0 + y + j) * T + t0 + x];
    __syncthreads();
    #pragma unroll
    for (int j = 0; j < 32; j += 8)
        g_uth[(size_t)(t0 + y + j) * C + c0 + x] = __float2half(tile[x][y + j]);
}

// g_v[0][:] += W_A(fp32) @ x0  (exact x0 injection; runs AFTER vgemm)
__global__ void ax0_kernel(const float* __restrict__ WA, const float* __restrict__ x0) {
    const int r = blockIdx.x * 8 + (threadIdx.x >> 5);
    const int lane = threadIdx.x & 31;
    const float* row = WA + (size_t)r * D;
    float a = 0.f;
    #pragma unroll 4
    for (int k = lane; k < D; k += 32) a += row[k] * x0[k];
    #pragma unroll
    for (int off = 16; off > 0; off >>= 1) a += __shfl_down_sync(0xffffffffu, a, off);
    if (lane == 0) g_v[r] += a;
}

// Zero initial state Y[0] and barrier state (must run every replay)
__global__ void zero_kernel() {
    size_t i = (size_t)blockIdx.x * blockDim.x + threadIdx.x;
    uint32_t* y0 = reinterpret_cast<uint32_t*>(g_Y[0]);
    if (i < (size_t)NCH * D / 2) y0[i] = 0u;
    if (i == 0) { g_count = 0u; g_gen = 0u; }
}

// ---------------------------------------------------------------------------
// Entry point
// ---------------------------------------------------------------------------
extern "C" void kernel_launch(void* const* d_in, const int* in_sizes, int n_in,
                              void* d_out, int out_size)
{
    const float* x0 = (const float*)d_in[0];   // [D]
    const float* u  = (const float*)d_in[1];   // [C, T]
    const float* WA = (const float*)d_in[2];   // [D, D]
    const float* bA = (const float*)d_in[3];   // [D]
    const float* WB = (const float*)d_in[4];   // [D, C]
    const float* bB = (const float*)d_in[5];   // [D]
    float* out = (float*)d_out;                // [T, D]
    (void)in_sizes; (void)n_in; (void)out_size;

    // Opt into >48KB dynamic smem. Skip while a graph capture is active
    // (attributes were already applied during the correctness call).
    cudaStreamCaptureStatus cap = cudaStreamCaptureStatusNone;
    cudaStreamIsCapturing(0, &cap);
    if (cap == cudaStreamCaptureStatusNone) {
        cudaFuncSetAttribute(scan_persist_kernel,
                             cudaFuncAttributeMaxDynamicSharedMemorySize, SMEM_TOTAL);
        cudaFuncSetAttribute(vgemm_tc_kernel,
                             cudaFuncAttributeMaxDynamicSharedMemorySize, SMEM_TOTAL);
    }

    // Setup
    convA_kernel<<<(unsigned)((size_t)D * D / 4 / 256), 256>>>(WA);
    convWB_kernel<<<(unsigned)((size_t)D * C / 4 / 256), 256>>>(WB);
    transu_kernel<<<dim3(T / 32, C / 32), dim3(32, 8)>>>(u);
    vgemm_tc_kernel<<<MT * (T / 64), 256, SMEM_TOTAL>>>(bA, bB);
    ax0_kernel<<<D / 8, 256>>>(WA, x0);
    zero_kernel<<<1024, 256>>>();

    // All 50 batched-recurrence steps in one persistent launch
    scan_persist_kernel<<<MT * KSPLIT, 256, SMEM_TOTAL>>>(out);
}